// round 15
// baseline (speedup 1.0000x reference)
#include <cuda_runtime.h>
#include <cuda_fp16.h>
#include <cstdint>

// GIN: h = GINConv(x) -> GINConv(h) -> relu(Wf1) -> Wf2
// N=100000, E=1600000, D_IN=128, D_H=256, D_OUT=64
// All intermediates fp16 (same 10-bit mantissa as tf32), fp32 accumulation.

static constexpr int NN = 100000;
static constexpr int DHMAX = 256;
static constexpr int CAP = 96;
static constexpr int WTOT = 32768 + 65536 * 4 + 16384;  // 311296

// Scratch (no cudaMalloc allowed)
__device__ __align__(128) __half g_bufA[(size_t)NN * DHMAX];
__device__ __align__(128) __half g_bufB[(size_t)NN * DHMAX];  // also holds xh pre-GEMM1
__device__ __align__(128) __half g_bufC[(size_t)NN * DHMAX];
__device__ __align__(128) int2   g_ev[(size_t)NN * CAP];
__device__ __align__(128) __half g_wcvt[WTOT];
__device__ int g_cnt[NN];

// ---------------------------------------------------------------------------
// Prepass launch 1: weight fp16 conversion + zero per-node counters
// ---------------------------------------------------------------------------
__global__ void wcvt_zero_kernel(const float* __restrict__ W1a, const float* __restrict__ W2a,
                                 const float* __restrict__ W1b, const float* __restrict__ W2b,
                                 const float* __restrict__ Wf1, const float* __restrict__ Wf2,
                                 __half* __restrict__ out, int* __restrict__ cnt, int n) {
    int i = blockIdx.x * blockDim.x + threadIdx.x;
    if (i < n) cnt[i] = 0;
    if (i >= WTOT) return;
    const float* src; int off;
    if      (i <  32768) { src = W1a; off = 0;      }
    else if (i <  98304) { src = W2a; off = 32768;  }
    else if (i < 163840) { src = W1b; off = 98304;  }
    else if (i < 229376) { src = W2b; off = 163840; }
    else if (i < 294912) { src = Wf1; off = 229376; }
    else                 { src = Wf2; off = 294912; }
    out[i] = __float2half_rn(src[i - off]);
}

// ---------------------------------------------------------------------------
// Prepass launch 2: scatter edges into padded per-node buckets
// ---------------------------------------------------------------------------
__global__ void fill_direct_kernel(const int* __restrict__ row, const int* __restrict__ col,
                                   const float* __restrict__ vals, int* __restrict__ cnt,
                                   int2* __restrict__ ev, int E) {
    int e = blockIdx.x * blockDim.x + threadIdx.x;
    if (e < E) {
        int r = row[e];
        int pos = atomicAdd(&cnt[r], 1);
        if (pos < CAP)
            ev[(size_t)r * CAP + pos] = make_int2(col[e], __float_as_int(vals[e]));
    }
}

// ---------------------------------------------------------------------------
// Prepass launch 3: convert x (fp32, N x 128) to fp16
// ---------------------------------------------------------------------------
__global__ void xcvt_kernel(const float* __restrict__ x, __half* __restrict__ xh,
                            int total4) {
    int i = blockIdx.x * blockDim.x + threadIdx.x;
    if (i >= total4) return;
    float4 v = __ldg((const float4*)x + i);
    __half2 h0 = __floats2half2_rn(v.x, v.y);
    __half2 h1 = __floats2half2_rn(v.z, v.w);
    uint2 o;
    o.x = *(uint32_t*)&h0; o.y = *(uint32_t*)&h1;
    ((uint2*)xh)[i] = o;
}

// ---------------------------------------------------------------------------
// fp16-gather SpMM, fused eps-residual, fp32 accumulation, fp16 output.
// One warp per node; edge loop unrolled x4 (4 independent gathers in flight
// to cover L2 latency — the loop is latency-bound, not BW-bound).
// ---------------------------------------------------------------------------
template<int D> struct VecSel;
template<> struct VecSel<128> { using T = uint2; };
template<> struct VecSel<256> { using T = uint4; };

template<int D>
__global__ __launch_bounds__(256)
void spmm_h_kernel(const int* __restrict__ cnt, const int2* __restrict__ ev,
                   const __half* __restrict__ x, const float* __restrict__ eps,
                   __half* __restrict__ h, int n) {
    using Vec = typename VecSel<D>::T;
    constexpr int NH2 = D / 64;          // half2 per lane
    int warp = (blockIdx.x * blockDim.x + threadIdx.x) >> 5;
    int lane = threadIdx.x & 31;
    if (warp >= n) return;

    float s = 1.0f + eps[0];
    float2 acc[NH2];
    {
        Vec v = __ldg((const Vec*)(x + (size_t)warp * D) + lane);
        const __half2* hp = (const __half2*)&v;
#pragma unroll
        for (int i = 0; i < NH2; i++) {
            float2 f = __half22float2(hp[i]);
            acc[i] = make_float2(s * f.x, s * f.y);
        }
    }

    const int2* eb = ev + (size_t)warp * CAP;
    int len = min(cnt[warp], CAP);
    int e = 0;
    // x4 unrolled body: all 4 edge metas then all 4 gathers issued before use
    for (; e + 4 <= len; e += 4) {
        int2 m0 = __ldg(eb + e + 0);
        int2 m1 = __ldg(eb + e + 1);
        int2 m2 = __ldg(eb + e + 2);
        int2 m3 = __ldg(eb + e + 3);
        Vec g0 = __ldg((const Vec*)(x + (size_t)m0.x * D) + lane);
        Vec g1 = __ldg((const Vec*)(x + (size_t)m1.x * D) + lane);
        Vec g2 = __ldg((const Vec*)(x + (size_t)m2.x * D) + lane);
        Vec g3 = __ldg((const Vec*)(x + (size_t)m3.x * D) + lane);
        float v0 = __int_as_float(m0.y);
        float v1 = __int_as_float(m1.y);
        float v2 = __int_as_float(m2.y);
        float v3 = __int_as_float(m3.y);
        const __half2* p0 = (const __half2*)&g0;
        const __half2* p1 = (const __half2*)&g1;
        const __half2* p2 = (const __half2*)&g2;
        const __half2* p3 = (const __half2*)&g3;
#pragma unroll
        for (int i = 0; i < NH2; i++) {
            float2 f0 = __half22float2(p0[i]);
            float2 f1 = __half22float2(p1[i]);
            float2 f2 = __half22float2(p2[i]);
            float2 f3 = __half22float2(p3[i]);
            acc[i].x = fmaf(v0, f0.x, acc[i].x);
            acc[i].y = fmaf(v0, f0.y, acc[i].y);
            acc[i].x = fmaf(v1, f1.x, acc[i].x);
            acc[i].y = fmaf(v1, f1.y, acc[i].y);
            acc[i].x = fmaf(v2, f2.x, acc[i].x);
            acc[i].y = fmaf(v2, f2.y, acc[i].y);
            acc[i].x = fmaf(v3, f3.x, acc[i].x);
            acc[i].y = fmaf(v3, f3.y, acc[i].y);
        }
    }
    for (; e < len; e++) {
        int2 m0 = __ldg(eb + e);
        float v0 = __int_as_float(m0.y);
        Vec g0 = __ldg((const Vec*)(x + (size_t)m0.x * D) + lane);
        const __half2* p0 = (const __half2*)&g0;
#pragma unroll
        for (int i = 0; i < NH2; i++) {
            float2 f0 = __half22float2(p0[i]);
            acc[i].x = fmaf(v0, f0.x, acc[i].x);
            acc[i].y = fmaf(v0, f0.y, acc[i].y);
        }
    }

    Vec o;
    uint32_t* op = (uint32_t*)&o;
#pragma unroll
    for (int i = 0; i < NH2; i++) {
        __half2 hv = __floats2half2_rn(acc[i].x, acc[i].y);
        op[i] = *(uint32_t*)&hv;
    }
    ((Vec*)(h + (size_t)warp * D))[lane] = o;
}

// ---------------------------------------------------------------------------
// FP16 tensor-core GEMM (mma.sync.m16n8k16.f32.f16.f16.f32):
// BM=128 x BN, 256 threads, register-staged global prefetch + double smem
// buffer, one barrier per k-tile (BK=64 fp16 = 128B rows).
// C[n, Fout] = A[n, K] @ W[Fout, K]^T + bias  (opt ReLU; out fp16 or fp32)
// ---------------------------------------------------------------------------
#define MMA_F16(d, a, b0, b1)                                                      \
    asm volatile(                                                                  \
        "mma.sync.aligned.m16n8k16.row.col.f32.f16.f16.f32 "                       \
        "{%0,%1,%2,%3},{%4,%5,%6,%7},{%8,%9},{%0,%1,%2,%3};"                       \
        : "+f"((d)[0]), "+f"((d)[1]), "+f"((d)[2]), "+f"((d)[3])                   \
        : "r"((a)[0]), "r"((a)[1]), "r"((a)[2]), "r"((a)[3]), "r"(b0), "r"(b1))

#define LDSM_X4(r, addr)                                                           \
    asm volatile("ldmatrix.sync.aligned.m8n8.x4.shared.b16 {%0,%1,%2,%3},[%4];"    \
                 : "=r"((r)[0]), "=r"((r)[1]), "=r"((r)[2]), "=r"((r)[3])          \
                 : "r"(addr))

template<int BN, bool RELU, bool HOUT>
__global__ __launch_bounds__(256)
void gemm_f16_kernel(const __half* __restrict__ A, const __half* __restrict__ W,
                     const float* __restrict__ bias, void* __restrict__ Cv,
                     int n, int K, int Fout) {
    constexpr int BM = 128, PAD = 36;            // 144B row stride (u32 units)
    constexpr int WN = BN / 2;
    constexpr int NB = WN / 8;
    constexpr int NB16 = WN / 16;
    constexpr int AL4 = 4;
    constexpr int BL4 = BN * 8 / 256;            // 4 or 2
    constexpr int ASZ = BM * PAD;
    constexpr int BSZ = BN * PAD;

    extern __shared__ uint32_t sm[];
    uint32_t* As0 = sm;
    uint32_t* Bs0 = sm + 2 * ASZ;

    const int tid = threadIdx.x;
    const int lane = tid & 31;
    const int wid = tid >> 5;
    const int wm = (wid & 3) * 32;
    const int bn = (wid >> 2) * WN;
    const int rowBase = blockIdx.y * BM;
    const int colBase = blockIdx.x * BN;

    const char* Ab = (const char*)A;
    const char* Wb = (const char*)W;
    const size_t rowBytes = (size_t)K * 2;

    uint4 ra[AL4], rb[BL4];

    auto ldAB = [&](int kt) {
        const size_t kOff = (size_t)kt * 128;    // 64 fp16 = 128 bytes
#pragma unroll
        for (int l = 0; l < AL4; l++) {
            int idx = tid + l * 256;
            int r = idx >> 3, c = (idx & 7) * 16;
            int gr = rowBase + r;
            ra[l] = (gr < n) ? *(const uint4*)(Ab + (size_t)gr * rowBytes + kOff + c)
                             : make_uint4(0u, 0u, 0u, 0u);
        }
#pragma unroll
        for (int l = 0; l < BL4; l++) {
            int idx = tid + l * 256;
            int r = idx >> 3, c = (idx & 7) * 16;
            rb[l] = *(const uint4*)(Wb + (size_t)(colBase + r) * rowBytes + kOff + c);
        }
    };
    auto stAB = [&](int stage) {
        uint32_t* Ad = As0 + stage * ASZ;
        uint32_t* Bd = Bs0 + stage * BSZ;
#pragma unroll
        for (int l = 0; l < AL4; l++) {
            int idx = tid + l * 256;
            int r = idx >> 3, c = (idx & 7) * 4;
            *(uint4*)&Ad[r * PAD + c] = ra[l];
        }
#pragma unroll
        for (int l = 0; l < BL4; l++) {
            int idx = tid + l * 256;
            int r = idx >> 3, c = (idx & 7) * 4;
            *(uint4*)&Bd[r * PAD + c] = rb[l];
        }
    };

    const uint32_t smBase = (uint32_t)__cvta_generic_to_shared(sm);
    const uint32_t aTh = smBase +
        (uint32_t)(((wm + (lane & 15)) * PAD + (lane >> 4) * 4) * 4);
    const uint32_t bTh = smBase + (uint32_t)(2 * ASZ * 4) +
        (uint32_t)(((bn + (((lane >> 4) << 3) | (lane & 7))) * PAD +
                    ((lane >> 3) & 1) * 4) * 4);

    float acc[2][NB][4];
#pragma unroll
    for (int i = 0; i < 2; i++)
#pragma unroll
        for (int j = 0; j < NB; j++)
#pragma unroll
            for (int k = 0; k < 4; k++) acc[i][j][k] = 0.f;

    const int nk = K / 64;
    ldAB(0);
    stAB(0);
    __syncthreads();

    for (int kt = 0; kt < nk; kt++) {
        if (kt + 1 < nk) ldAB(kt + 1);   // global prefetch into regs

        const uint32_t aBase = aTh + (uint32_t)((kt & 1) * ASZ * 4);
        const uint32_t bBase = bTh + (uint32_t)((kt & 1) * BSZ * 4);
#pragma unroll
        for (int kk = 0; kk < 4; kk++) {
            uint32_t afr[2][4];
#pragma unroll
            for (int tm = 0; tm < 2; tm++)
                LDSM_X4(afr[tm], aBase + (uint32_t)(tm * 16 * PAD + kk * 8) * 4);
            uint32_t bfr[NB16][4];
#pragma unroll
            for (int j = 0; j < NB16; j++)
                LDSM_X4(bfr[j], bBase + (uint32_t)(j * 16 * PAD + kk * 8) * 4);
#pragma unroll
            for (int tm = 0; tm < 2; tm++)
#pragma unroll
                for (int j = 0; j < NB16; j++) {
                    MMA_F16(acc[tm][2 * j + 0], afr[tm], bfr[j][0], bfr[j][1]);
                    MMA_F16(acc[tm][2 * j + 1], afr[tm], bfr[j][2], bfr[j][3]);
                }
        }
        if (kt + 1 < nk) {
            stAB((kt + 1) & 1);
            __syncthreads();
        }
    }

#pragma unroll
    for (int tm = 0; tm < 2; tm++) {
#pragma unroll
        for (int half = 0; half < 2; half++) {
            int gr = rowBase + wm + tm * 16 + (lane >> 2) + half * 8;
            if (gr >= n) continue;
#pragma unroll
            for (int nt = 0; nt < NB; nt++) {
                int gc = colBase + bn + nt * 8 + 2 * (lane & 3);
                float2 bv = *(const float2*)(bias + gc);
                float o0 = acc[tm][nt][half * 2 + 0] + bv.x;
                float o1 = acc[tm][nt][half * 2 + 1] + bv.y;
                if (RELU) { o0 = fmaxf(o0, 0.f); o1 = fmaxf(o1, 0.f); }
                if (HOUT) {
                    __half2 hv = __floats2half2_rn(o0, o1);
                    *(__half2*)((__half*)Cv + (size_t)gr * Fout + gc) = hv;
                } else {
                    *(float2*)((float*)Cv + (size_t)gr * Fout + gc) =
                        make_float2(o0, o1);
                }
            }
        }
    }
}

// ---------------------------------------------------------------------------
extern "C" void kernel_launch(void* const* d_in, const int* in_sizes, int n_in,
                              void* d_out, int out_size) {
    const float* x    = (const float*)d_in[0];
    const int*   row  = (const int*)  d_in[1];
    const int*   col  = (const int*)  d_in[2];
    const float* vals = (const float*)d_in[3];
    const float* eps0 = (const float*)d_in[4];
    const float* W1a  = (const float*)d_in[5];
    const float* b1a  = (const float*)d_in[6];
    const float* W2a  = (const float*)d_in[7];
    const float* b2a  = (const float*)d_in[8];
    const float* eps1 = (const float*)d_in[9];
    const float* W1b  = (const float*)d_in[10];
    const float* b1b  = (const float*)d_in[11];
    const float* W2b  = (const float*)d_in[12];
    const float* b2b  = (const float*)d_in[13];
    const float* Wf1  = (const float*)d_in[14];
    const float* bf1  = (const float*)d_in[15];
    const float* Wf2  = (const float*)d_in[16];
    const float* bf2  = (const float*)d_in[17];
    float* out = (float*)d_out;

    const int n = NN;
    const int E = in_sizes[1];

    __half *bufA, *bufB, *bufC, *wc;
    int* cnt;
    int2* ev;
    cudaGetSymbolAddress((void**)&bufA, g_bufA);
    cudaGetSymbolAddress((void**)&bufB, g_bufB);
    cudaGetSymbolAddress((void**)&bufC, g_bufC);
    cudaGetSymbolAddress((void**)&wc, g_wcvt);
    cudaGetSymbolAddress((void**)&cnt, g_cnt);
    cudaGetSymbolAddress((void**)&ev, g_ev);

    // fp16 weight pointers
    const __half* wW1a = wc + 0;
    const __half* wW2a = wc + 32768;
    const __half* wW1b = wc + 98304;
    const __half* wW2b = wc + 163840;
    const __half* wWf1 = wc + 229376;
    const __half* wWf2 = wc + 294912;

    constexpr int PAD = 36;
    const int smem128 = (2 * 128 * PAD + 2 * 128 * PAD) * 4;  // 73728
    const int smem64  = (2 * 128 * PAD + 2 * 64 * PAD) * 4;   // 55296
    cudaFuncSetAttribute(gemm_f16_kernel<128, true,  true >,
                         cudaFuncAttributeMaxDynamicSharedMemorySize, smem128);
    cudaFuncSetAttribute(gemm_f16_kernel<128, false, true >,
                         cudaFuncAttributeMaxDynamicSharedMemorySize, smem128);
    cudaFuncSetAttribute(gemm_f16_kernel<64,  false, false>,
                         cudaFuncAttributeMaxDynamicSharedMemorySize, smem64);

    const int mblocks = (n + 127) / 128;   // 782
    dim3 g256(2, mblocks);   // x = col tiles, y = row tiles
    dim3 g64(1, mblocks);
    const int spmm_blocks = (n + 7) / 8;   // 1 warp/node

    // ---- Prepass: 3 launches ----
    wcvt_zero_kernel<<<(WTOT + 255) / 256, 256>>>(W1a, W2a, W1b, W2b, Wf1, Wf2,
                                                  wc, cnt, n);
    fill_direct_kernel<<<(E + 255) / 256, 256>>>(row, col, vals, cnt, ev, E);
    const int x4 = n * 128 / 4;
    xcvt_kernel<<<(x4 + 255) / 256, 256>>>(x, bufB, x4);   // xh staged in bufB

    // ---- GIN layer 1 (D=128, fp16 gather) ----
    spmm_h_kernel<128><<<spmm_blocks, 256>>>(cnt, ev, bufB, eps0, bufA, n);
    gemm_f16_kernel<128, true,  true ><<<g256, 256, smem128>>>(bufA, wW1a, b1a, bufB, n, 128, 256);
    gemm_f16_kernel<128, false, true ><<<g256, 256, smem128>>>(bufB, wW2a, b2a, bufC, n, 256, 256);

    // ---- GIN layer 2 (D=256, fp16 gather) ----
    spmm_h_kernel<256><<<spmm_blocks, 256>>>(cnt, ev, bufC, eps1, bufA, n);
    gemm_f16_kernel<128, true,  true ><<<g256, 256, smem128>>>(bufA, wW1b, b1b, bufB, n, 256, 256);
    gemm_f16_kernel<128, false, true ><<<g256, 256, smem128>>>(bufB, wW2b, b2b, bufC, n, 256, 256);

    // ---- Final MLP ----
    gemm_f16_kernel<128, true,  true ><<<g256, 256, smem128>>>(bufC, wWf1, bf1, bufB, n, 256, 256);
    gemm_f16_kernel<64,  false, false><<<g64, 256, smem64>>>(bufB, wWf2, bf2, out, n, 256, 64);
}

// round 16
// speedup vs baseline: 1.0532x; 1.0532x over previous
#include <cuda_runtime.h>
#include <cuda_fp16.h>
#include <cstdint>

// GIN: h = GINConv(x) -> GINConv(h) -> relu(Wf1) -> Wf2
// N=100000, E=1600000, D_IN=128, D_H=256, D_OUT=64
// All intermediates fp16 (same 10-bit mantissa as tf32), fp32 accumulation.

static constexpr int NN = 100000;
static constexpr int DHMAX = 256;
static constexpr int CAP = 96;
static constexpr int WTOT = 32768 + 65536 * 4 + 16384;  // 311296

// Scratch (no cudaMalloc allowed)
__device__ __align__(128) __half g_bufA[(size_t)NN * DHMAX];
__device__ __align__(128) __half g_bufB[(size_t)NN * DHMAX];  // also holds xh pre-GEMM1
__device__ __align__(128) __half g_bufC[(size_t)NN * DHMAX];
__device__ __align__(128) int2   g_ev[(size_t)NN * CAP];
__device__ __align__(128) __half g_wcvt[WTOT];
__device__ int g_cnt[NN];

// ---------------------------------------------------------------------------
// Prepass launch 1: weight fp16 conversion + zero per-node counters
// ---------------------------------------------------------------------------
__global__ void wcvt_zero_kernel(const float* __restrict__ W1a, const float* __restrict__ W2a,
                                 const float* __restrict__ W1b, const float* __restrict__ W2b,
                                 const float* __restrict__ Wf1, const float* __restrict__ Wf2,
                                 __half* __restrict__ out, int* __restrict__ cnt, int n) {
    int i = blockIdx.x * blockDim.x + threadIdx.x;
    if (i < n) cnt[i] = 0;
    if (i >= WTOT) return;
    const float* src; int off;
    if      (i <  32768) { src = W1a; off = 0;      }
    else if (i <  98304) { src = W2a; off = 32768;  }
    else if (i < 163840) { src = W1b; off = 98304;  }
    else if (i < 229376) { src = W2b; off = 163840; }
    else if (i < 294912) { src = Wf1; off = 229376; }
    else                 { src = Wf2; off = 294912; }
    out[i] = __float2half_rn(src[i - off]);
}

// ---------------------------------------------------------------------------
// Prepass launch 2: scatter edges into padded per-node buckets
// ---------------------------------------------------------------------------
__global__ void fill_direct_kernel(const int* __restrict__ row, const int* __restrict__ col,
                                   const float* __restrict__ vals, int* __restrict__ cnt,
                                   int2* __restrict__ ev, int E) {
    int e = blockIdx.x * blockDim.x + threadIdx.x;
    if (e < E) {
        int r = row[e];
        int pos = atomicAdd(&cnt[r], 1);
        if (pos < CAP)
            ev[(size_t)r * CAP + pos] = make_int2(col[e], __float_as_int(vals[e]));
    }
}

// ---------------------------------------------------------------------------
// Prepass launch 3: convert x (fp32, N x 128) to fp16
// ---------------------------------------------------------------------------
__global__ void xcvt_kernel(const float* __restrict__ x, __half* __restrict__ xh,
                            int total4) {
    int i = blockIdx.x * blockDim.x + threadIdx.x;
    if (i >= total4) return;
    float4 v = __ldg((const float4*)x + i);
    __half2 h0 = __floats2half2_rn(v.x, v.y);
    __half2 h1 = __floats2half2_rn(v.z, v.w);
    uint2 o;
    o.x = *(uint32_t*)&h0; o.y = *(uint32_t*)&h1;
    ((uint2*)xh)[i] = o;
}

// ---------------------------------------------------------------------------
// fp16-gather SpMM, fused eps-residual, fp32 accumulation, fp16 output.
// TWO nodes per warp (16 lanes each) -> 2 independent edge chains per warp;
// edge loop unrolled x2 -> 4 gathers in flight per warp with no extra regs.
// Each half-warp gather: 16 lanes x 16B (uint4) per chunk, fully coalesced.
// ---------------------------------------------------------------------------
template<int D>
__global__ __launch_bounds__(256)
void spmm_hw_kernel(const int* __restrict__ cnt, const int2* __restrict__ ev,
                    const __half* __restrict__ x, const float* __restrict__ eps,
                    __half* __restrict__ h, int n) {
    constexpr int NV = D / 128;          // uint4 per lane (16 lanes x 8 fp16)
    constexpr int NH2 = 4 * NV;          // half2 per lane
    int gw = (blockIdx.x * blockDim.x + threadIdx.x) >> 5;
    int lane = threadIdx.x & 31;
    int node = gw * 2 + (lane >> 4);
    int l16 = lane & 15;
    if (node >= n) return;

    float s = 1.0f + eps[0];
    float2 acc[NH2];
    {
        uint4 v[NV];
#pragma unroll
        for (int j = 0; j < NV; j++)
            v[j] = __ldg((const uint4*)(x + (size_t)node * D) + l16 * NV + j);
        const __half2* hp = (const __half2*)v;
#pragma unroll
        for (int i = 0; i < NH2; i++) {
            float2 f = __half22float2(hp[i]);
            acc[i] = make_float2(s * f.x, s * f.y);
        }
    }

    const int2* eb = ev + (size_t)node * CAP;
    int len = min(cnt[node], CAP);
    int e = 0;
    for (; e + 2 <= len; e += 2) {
        int2 m0 = __ldg(eb + e);
        int2 m1 = __ldg(eb + e + 1);
        uint4 g0[NV], g1[NV];
#pragma unroll
        for (int j = 0; j < NV; j++) {
            g0[j] = __ldg((const uint4*)(x + (size_t)m0.x * D) + l16 * NV + j);
            g1[j] = __ldg((const uint4*)(x + (size_t)m1.x * D) + l16 * NV + j);
        }
        float v0 = __int_as_float(m0.y);
        float v1 = __int_as_float(m1.y);
        const __half2* p0 = (const __half2*)g0;
        const __half2* p1 = (const __half2*)g1;
#pragma unroll
        for (int i = 0; i < NH2; i++) {
            float2 f0 = __half22float2(p0[i]);
            float2 f1 = __half22float2(p1[i]);
            acc[i].x = fmaf(v0, f0.x, acc[i].x);
            acc[i].y = fmaf(v0, f0.y, acc[i].y);
            acc[i].x = fmaf(v1, f1.x, acc[i].x);
            acc[i].y = fmaf(v1, f1.y, acc[i].y);
        }
    }
    if (e < len) {
        int2 m0 = __ldg(eb + e);
        float v0 = __int_as_float(m0.y);
        uint4 g0[NV];
#pragma unroll
        for (int j = 0; j < NV; j++)
            g0[j] = __ldg((const uint4*)(x + (size_t)m0.x * D) + l16 * NV + j);
        const __half2* p0 = (const __half2*)g0;
#pragma unroll
        for (int i = 0; i < NH2; i++) {
            float2 f0 = __half22float2(p0[i]);
            acc[i].x = fmaf(v0, f0.x, acc[i].x);
            acc[i].y = fmaf(v0, f0.y, acc[i].y);
        }
    }

    uint4 o[NV];
    uint32_t* op = (uint32_t*)o;
#pragma unroll
    for (int i = 0; i < NH2; i++) {
        __half2 hv = __floats2half2_rn(acc[i].x, acc[i].y);
        op[i] = *(uint32_t*)&hv;
    }
#pragma unroll
    for (int j = 0; j < NV; j++)
        ((uint4*)(h + (size_t)node * D))[l16 * NV + j] = o[j];
}

// ---------------------------------------------------------------------------
// FP16 tensor-core GEMM (mma.sync.m16n8k16.f32.f16.f16.f32):
// BM=128 x BN, 256 threads, register-staged global prefetch + double smem
// buffer, one barrier per k-tile (BK=64 fp16 = 128B rows).
// C[n, Fout] = A[n, K] @ W[Fout, K]^T + bias  (opt ReLU; out fp16 or fp32)
// ---------------------------------------------------------------------------
#define MMA_F16(d, a, b0, b1)                                                      \
    asm volatile(                                                                  \
        "mma.sync.aligned.m16n8k16.row.col.f32.f16.f16.f32 "                       \
        "{%0,%1,%2,%3},{%4,%5,%6,%7},{%8,%9},{%0,%1,%2,%3};"                       \
        : "+f"((d)[0]), "+f"((d)[1]), "+f"((d)[2]), "+f"((d)[3])                   \
        : "r"((a)[0]), "r"((a)[1]), "r"((a)[2]), "r"((a)[3]), "r"(b0), "r"(b1))

#define LDSM_X4(r, addr)                                                           \
    asm volatile("ldmatrix.sync.aligned.m8n8.x4.shared.b16 {%0,%1,%2,%3},[%4];"    \
                 : "=r"((r)[0]), "=r"((r)[1]), "=r"((r)[2]), "=r"((r)[3])          \
                 : "r"(addr))

template<int BN, bool RELU, bool HOUT>
__global__ __launch_bounds__(256)
void gemm_f16_kernel(const __half* __restrict__ A, const __half* __restrict__ W,
                     const float* __restrict__ bias, void* __restrict__ Cv,
                     int n, int K, int Fout) {
    constexpr int BM = 128, PAD = 36;            // 144B row stride (u32 units)
    constexpr int WN = BN / 2;
    constexpr int NB = WN / 8;
    constexpr int NB16 = WN / 16;
    constexpr int AL4 = 4;
    constexpr int BL4 = BN * 8 / 256;            // 4 or 2
    constexpr int ASZ = BM * PAD;
    constexpr int BSZ = BN * PAD;

    extern __shared__ uint32_t sm[];
    uint32_t* As0 = sm;
    uint32_t* Bs0 = sm + 2 * ASZ;

    const int tid = threadIdx.x;
    const int lane = tid & 31;
    const int wid = tid >> 5;
    const int wm = (wid & 3) * 32;
    const int bn = (wid >> 2) * WN;
    const int rowBase = blockIdx.y * BM;
    const int colBase = blockIdx.x * BN;

    const char* Ab = (const char*)A;
    const char* Wb = (const char*)W;
    const size_t rowBytes = (size_t)K * 2;

    uint4 ra[AL4], rb[BL4];

    auto ldAB = [&](int kt) {
        const size_t kOff = (size_t)kt * 128;    // 64 fp16 = 128 bytes
#pragma unroll
        for (int l = 0; l < AL4; l++) {
            int idx = tid + l * 256;
            int r = idx >> 3, c = (idx & 7) * 16;
            int gr = rowBase + r;
            ra[l] = (gr < n) ? *(const uint4*)(Ab + (size_t)gr * rowBytes + kOff + c)
                             : make_uint4(0u, 0u, 0u, 0u);
        }
#pragma unroll
        for (int l = 0; l < BL4; l++) {
            int idx = tid + l * 256;
            int r = idx >> 3, c = (idx & 7) * 16;
            rb[l] = *(const uint4*)(Wb + (size_t)(colBase + r) * rowBytes + kOff + c);
        }
    };
    auto stAB = [&](int stage) {
        uint32_t* Ad = As0 + stage * ASZ;
        uint32_t* Bd = Bs0 + stage * BSZ;
#pragma unroll
        for (int l = 0; l < AL4; l++) {
            int idx = tid + l * 256;
            int r = idx >> 3, c = (idx & 7) * 4;
            *(uint4*)&Ad[r * PAD + c] = ra[l];
        }
#pragma unroll
        for (int l = 0; l < BL4; l++) {
            int idx = tid + l * 256;
            int r = idx >> 3, c = (idx & 7) * 4;
            *(uint4*)&Bd[r * PAD + c] = rb[l];
        }
    };

    const uint32_t smBase = (uint32_t)__cvta_generic_to_shared(sm);
    const uint32_t aTh = smBase +
        (uint32_t)(((wm + (lane & 15)) * PAD + (lane >> 4) * 4) * 4);
    const uint32_t bTh = smBase + (uint32_t)(2 * ASZ * 4) +
        (uint32_t)(((bn + (((lane >> 4) << 3) | (lane & 7))) * PAD +
                    ((lane >> 3) & 1) * 4) * 4);

    float acc[2][NB][4];
#pragma unroll
    for (int i = 0; i < 2; i++)
#pragma unroll
        for (int j = 0; j < NB; j++)
#pragma unroll
            for (int k = 0; k < 4; k++) acc[i][j][k] = 0.f;

    const int nk = K / 64;
    ldAB(0);
    stAB(0);
    __syncthreads();

    for (int kt = 0; kt < nk; kt++) {
        if (kt + 1 < nk) ldAB(kt + 1);   // global prefetch into regs

        const uint32_t aBase = aTh + (uint32_t)((kt & 1) * ASZ * 4);
        const uint32_t bBase = bTh + (uint32_t)((kt & 1) * BSZ * 4);
#pragma unroll
        for (int kk = 0; kk < 4; kk++) {
            uint32_t afr[2][4];
#pragma unroll
            for (int tm = 0; tm < 2; tm++)
                LDSM_X4(afr[tm], aBase + (uint32_t)(tm * 16 * PAD + kk * 8) * 4);
            uint32_t bfr[NB16][4];
#pragma unroll
            for (int j = 0; j < NB16; j++)
                LDSM_X4(bfr[j], bBase + (uint32_t)(j * 16 * PAD + kk * 8) * 4);
#pragma unroll
            for (int tm = 0; tm < 2; tm++)
#pragma unroll
                for (int j = 0; j < NB16; j++) {
                    MMA_F16(acc[tm][2 * j + 0], afr[tm], bfr[j][0], bfr[j][1]);
                    MMA_F16(acc[tm][2 * j + 1], afr[tm], bfr[j][2], bfr[j][3]);
                }
        }
        if (kt + 1 < nk) {
            stAB((kt + 1) & 1);
            __syncthreads();
        }
    }

#pragma unroll
    for (int tm = 0; tm < 2; tm++) {
#pragma unroll
        for (int half = 0; half < 2; half++) {
            int gr = rowBase + wm + tm * 16 + (lane >> 2) + half * 8;
            if (gr >= n) continue;
#pragma unroll
            for (int nt = 0; nt < NB; nt++) {
                int gc = colBase + bn + nt * 8 + 2 * (lane & 3);
                float2 bv = *(const float2*)(bias + gc);
                float o0 = acc[tm][nt][half * 2 + 0] + bv.x;
                float o1 = acc[tm][nt][half * 2 + 1] + bv.y;
                if (RELU) { o0 = fmaxf(o0, 0.f); o1 = fmaxf(o1, 0.f); }
                if (HOUT) {
                    __half2 hv = __floats2half2_rn(o0, o1);
                    *(__half2*)((__half*)Cv + (size_t)gr * Fout + gc) = hv;
                } else {
                    *(float2*)((float*)Cv + (size_t)gr * Fout + gc) =
                        make_float2(o0, o1);
                }
            }
        }
    }
}

// ---------------------------------------------------------------------------
extern "C" void kernel_launch(void* const* d_in, const int* in_sizes, int n_in,
                              void* d_out, int out_size) {
    const float* x    = (const float*)d_in[0];
    const int*   row  = (const int*)  d_in[1];
    const int*   col  = (const int*)  d_in[2];
    const float* vals = (const float*)d_in[3];
    const float* eps0 = (const float*)d_in[4];
    const float* W1a  = (const float*)d_in[5];
    const float* b1a  = (const float*)d_in[6];
    const float* W2a  = (const float*)d_in[7];
    const float* b2a  = (const float*)d_in[8];
    const float* eps1 = (const float*)d_in[9];
    const float* W1b  = (const float*)d_in[10];
    const float* b1b  = (const float*)d_in[11];
    const float* W2b  = (const float*)d_in[12];
    const float* b2b  = (const float*)d_in[13];
    const float* Wf1  = (const float*)d_in[14];
    const float* bf1  = (const float*)d_in[15];
    const float* Wf2  = (const float*)d_in[16];
    const float* bf2  = (const float*)d_in[17];
    float* out = (float*)d_out;

    const int n = NN;
    const int E = in_sizes[1];

    __half *bufA, *bufB, *bufC, *wc;
    int* cnt;
    int2* ev;
    cudaGetSymbolAddress((void**)&bufA, g_bufA);
    cudaGetSymbolAddress((void**)&bufB, g_bufB);
    cudaGetSymbolAddress((void**)&bufC, g_bufC);
    cudaGetSymbolAddress((void**)&wc, g_wcvt);
    cudaGetSymbolAddress((void**)&cnt, g_cnt);
    cudaGetSymbolAddress((void**)&ev, g_ev);

    // fp16 weight pointers
    const __half* wW1a = wc + 0;
    const __half* wW2a = wc + 32768;
    const __half* wW1b = wc + 98304;
    const __half* wW2b = wc + 163840;
    const __half* wWf1 = wc + 229376;
    const __half* wWf2 = wc + 294912;

    constexpr int PAD = 36;
    const int smem128 = (2 * 128 * PAD + 2 * 128 * PAD) * 4;  // 73728
    const int smem64  = (2 * 128 * PAD + 2 * 64 * PAD) * 4;   // 55296
    cudaFuncSetAttribute(gemm_f16_kernel<128, true,  true >,
                         cudaFuncAttributeMaxDynamicSharedMemorySize, smem128);
    cudaFuncSetAttribute(gemm_f16_kernel<128, false, true >,
                         cudaFuncAttributeMaxDynamicSharedMemorySize, smem128);
    cudaFuncSetAttribute(gemm_f16_kernel<64,  false, false>,
                         cudaFuncAttributeMaxDynamicSharedMemorySize, smem64);

    const int mblocks = (n + 127) / 128;   // 782
    dim3 g256(2, mblocks);   // x = col tiles, y = row tiles
    dim3 g64(1, mblocks);
    const int spmm_blocks = (n + 15) / 16;   // 2 nodes/warp, 8 warps/block

    // ---- Prepass: 3 launches ----
    wcvt_zero_kernel<<<(WTOT + 255) / 256, 256>>>(W1a, W2a, W1b, W2b, Wf1, Wf2,
                                                  wc, cnt, n);
    fill_direct_kernel<<<(E + 255) / 256, 256>>>(row, col, vals, cnt, ev, E);
    const int x4 = n * 128 / 4;
    xcvt_kernel<<<(x4 + 255) / 256, 256>>>(x, bufB, x4);   // xh staged in bufB

    // ---- GIN layer 1 (D=128, fp16 gather) ----
    spmm_hw_kernel<128><<<spmm_blocks, 256>>>(cnt, ev, bufB, eps0, bufA, n);
    gemm_f16_kernel<128, true,  true ><<<g256, 256, smem128>>>(bufA, wW1a, b1a, bufB, n, 128, 256);
    gemm_f16_kernel<128, false, true ><<<g256, 256, smem128>>>(bufB, wW2a, b2a, bufC, n, 256, 256);

    // ---- GIN layer 2 (D=256, fp16 gather) ----
    spmm_hw_kernel<256><<<spmm_blocks, 256>>>(cnt, ev, bufC, eps1, bufA, n);
    gemm_f16_kernel<128, true,  true ><<<g256, 256, smem128>>>(bufA, wW1b, b1b, bufB, n, 256, 256);
    gemm_f16_kernel<128, false, true ><<<g256, 256, smem128>>>(bufB, wW2b, b2b, bufC, n, 256, 256);

    // ---- Final MLP ----
    gemm_f16_kernel<128, true,  true ><<<g256, 256, smem128>>>(bufC, wWf1, bf1, bufB, n, 256, 256);
    gemm_f16_kernel<64,  false, false><<<g64, 256, smem64>>>(bufB, wWf2, bf2, out, n, 256, 64);
}